// round 15
// baseline (speedup 1.0000x reference)
#include <cuda_runtime.h>

// 2x nearest-neighbor upsample — persistent grid-stride probe:
// in:  float32 [16, 64, 256, 256]  (1024 planes of 256x256)
// out: float32 [16, 64, 512, 512]
//
// Same per-element structure as the converged R9 kernel (output-quad
// indexing, 1 x LDG.64 + 2 x STG.128 per thread-iteration, all
// lane-contiguous), but launched as exactly one wave of persistent CTAs
// (148 SMs x 4 CTAs of 512 threads = 592 CTAs) with a grid-stride loop.
// Removes ~110 wave transitions of the one-shot launch. Predicted neutral;
// context: pinned at HBM mixed-stream ceiling (6.69 TB/s, DRAM 84.4%).

#define W_OUT4 128                  // float4 per output row (512/4)
#define NBLOCKS 592                 // 148 SMs x 4 CTAs (512 thr, 18 regs)

__global__ void __launch_bounds__(512) upsample2x_persist_kernel(
    const float2* __restrict__ in2, float4* __restrict__ out4, int total)
{
    int stride = gridDim.x * blockDim.x;    // 303,104
    for (int idx = blockIdx.x * blockDim.x + threadIdx.x;
         idx < total; idx += stride)
    {
        // idx -> (plane, h, ow4); input float2 index == idx
        int ow4   = idx & (W_OUT4 - 1);     // 0..127
        int h     = (idx >> 7) & 255;       // 0..255
        int plane = idx >> 15;              // 0..1023

        float2 v = in2[idx];
        float4 q = make_float4(v.x, v.x, v.y, v.y);

        // output row 2h of this plane, column ow4 (float4 units)
        long long base = ((long long)plane * 512 + 2 * h) * W_OUT4 + ow4;

        out4[base]          = q;   // row 2h
        out4[base + W_OUT4] = q;   // row 2h+1
    }
}

extern "C" void kernel_launch(void* const* d_in, const int* in_sizes, int n_in,
                              void* d_out, int out_size)
{
    const float2* in2 = (const float2*)d_in[0];
    float4* out4 = (float4*)d_out;

    int total = in_sizes[0] / 2;            // 33,554,432 work items

    upsample2x_persist_kernel<<<NBLOCKS, 512>>>(in2, out4, total);
}

// round 16
// speedup vs baseline: 1.1938x; 1.1938x over previous
#include <cuda_runtime.h>

// 2x nearest-neighbor upsample — FINAL (converged at HBM roofline):
// in:  float32 [16, 64, 256, 256]  (1024 planes of 256x256)
// out: float32 [16, 64, 512, 512]
//
// Thread indexing over OUTPUT quads (best of 8 measured variants):
//   idx -> (plane, h_in, ow4); input float2 index == idx (same linear index).
//   q = (x,x,y,y) stored to output rows 2h and 2h+1 at column ow4.
// Per warp: 1 x LDG.64 (256B contiguous) + 2 x STG.128 (512B contiguous).
//
// Converged: traffic at the 1.342 GB floor, 6.69 TB/s (84.4% of 8 TB/s),
// the measured ceiling for a 1:4 read:write mixed stream on this part.
// Probed and neutral/regressive: input-quad indexing (72.7% DRAM, 2x store
// wavefronts), streaming hints, 2-row unroll, STG.256, STG.256 x 2-row,
// 256-thread blocks, persistent grid-stride (71.6% DRAM — loop back-edge
// serializes memory issue; one-shot keeps ~2048 loads in flight per SM).

#define W_OUT4 128                  // float4 per output row (512/4)

__global__ void __launch_bounds__(512) upsample2x_outidx_kernel(
    const float2* __restrict__ in2, float4* __restrict__ out4, int total)
{
    int idx = blockIdx.x * blockDim.x + threadIdx.x;
    if (idx >= total) return;

    // idx -> (plane, h, ow4); input float2 index == idx
    int ow4   = idx & (W_OUT4 - 1);         // 0..127
    int h     = (idx >> 7) & 255;           // 0..255
    int plane = idx >> 15;                  // 0..1023

    float2 v = in2[idx];
    float4 q = make_float4(v.x, v.x, v.y, v.y);

    // output row 2h of this plane, column ow4 (float4 units)
    long long base = ((long long)plane * 512 + 2 * h) * W_OUT4 + ow4;

    out4[base]          = q;   // row 2h
    out4[base + W_OUT4] = q;   // row 2h+1
}

extern "C" void kernel_launch(void* const* d_in, const int* in_sizes, int n_in,
                              void* d_out, int out_size)
{
    const float2* in2 = (const float2*)d_in[0];
    float4* out4 = (float4*)d_out;

    int total = in_sizes[0] / 2;            // 33,554,432 threads
    int threads = 512;
    int blocks = (total + threads - 1) / threads;

    upsample2x_outidx_kernel<<<blocks, threads>>>(in2, out4, total);
}